// round 13
// baseline (speedup 1.0000x reference)
#include <cuda_runtime.h>

// SelMul: pair (i,j), i<=j, row-major triangular:
//   offset(i,j) = i*N - T(i+1) + j,  T(k) = k(k-1)/2,  value x[b,i]*x[b,j].
// x: (256,1024) fp32 -> out: (256,524800) fp32 (~537 MB). Store-bound.
//
// R12 = R11 (16-row tiles, 5 window LDG.128 per 16 aligned STG.128) with the
// w[20] bug fixed: D = {0,1,3,6,6,7,9,8,8,9,11,14,14,15,17,16}; row r=14 has
// D=17 so it needs w[17..20] -> 21 floats. R11 loaded only w[0..19] and pick5
// silently aliased index 20 to w[19] (rel_err 0.175). Fix: one extra SCALAR
// load w20 = x[i0+4t+20] (clamped), plus a statically bounds-checked pick6.
//
// Congruence (proven): T(i0+r+1) == T(r+1) (mod 4) for i0 % 8 == 0, so the
// first aligned j for row r is i0 + D(r), D(r) = r + ((T(r+1)&3 - r) & 3).
// Window t: w[k] = x[i0+4t+k]; row r stores float4 {w[D..D+3]} * x[i0+r] at
// out + base(r) + i0 + D + 4t (16B-aligned). Heads/tails scalar, same
// congruence (fj == i0 + D identically) -> exact coverage.

static constexpr int N       = 1024;
static constexpr int B       = 256;
static constexpr int TRI     = N * (N + 1) / 2;   // 524800
static constexpr int BB      = 4;                 // batches per block
static constexpr int THREADS = 256;
static constexpr int M4LAST  = N / 4 - 1;         // 255

__host__ __device__ constexpr int triang(int k) { return k * (k - 1) / 2; }
__host__ __device__ constexpr int Dof(int r) {
    return r + ((((triang(r + 1) & 3) - r) + 16) & 3);
}

// Select float K (0..15) from four float4s.
template <int K>
__device__ __forceinline__ float pick(const float4& a, const float4& b,
                                      const float4& c, const float4& d) {
    static_assert(K >= 0 && K <= 15);
    if constexpr (K == 0)  return a.x;
    else if constexpr (K == 1)  return a.y;
    else if constexpr (K == 2)  return a.z;
    else if constexpr (K == 3)  return a.w;
    else if constexpr (K == 4)  return b.x;
    else if constexpr (K == 5)  return b.y;
    else if constexpr (K == 6)  return b.z;
    else if constexpr (K == 7)  return b.w;
    else if constexpr (K == 8)  return c.x;
    else if constexpr (K == 9)  return c.y;
    else if constexpr (K == 10) return c.z;
    else if constexpr (K == 11) return c.w;
    else if constexpr (K == 12) return d.x;
    else if constexpr (K == 13) return d.y;
    else if constexpr (K == 14) return d.z;
    else return d.w;
}

// Select float K (0..20) from five float4s + one scalar (w[20]).
template <int K>
__device__ __forceinline__ float pick6(const float4& a, const float4& b,
                                       const float4& c, const float4& d,
                                       const float4& e, float w20) {
    static_assert(K >= 0 && K <= 20);          // bug class from R11: caught here
    if constexpr (K < 16)       return pick<K>(a, b, c, d);
    else if constexpr (K == 16) return e.x;
    else if constexpr (K == 17) return e.y;
    else if constexpr (K == 18) return e.z;
    else if constexpr (K == 19) return e.w;
    else                        return w20;
}

template <int R>
__device__ __forceinline__ void tile_row(bool lane_ok,
                                         const float4& w0, const float4& w1,
                                         const float4& w2, const float4& w3,
                                         const float4& w4, float w20,
                                         const float4& xq0, const float4& xq1,
                                         const float4& xq2, const float4& xq3,
                                         float* __restrict__ outb,
                                         int i0, int t) {
    constexpr int D = Dof(R);
    static_assert(D + 3 <= 20);
    const int v = N - i0 - D;            // 4*n_r; <= 0 for rows fully scalar
    if (lane_ok && v > 0 && t < (v >> 2)) {
        const int i = i0 + R;
        const float xi = pick<R>(xq0, xq1, xq2, xq3);       // x[i0+R]
        const int base = i * N - triang(i + 1);
        float4 o;
        o.x = pick6<D    >(w0, w1, w2, w3, w4, w20) * xi;
        o.y = pick6<D + 1>(w0, w1, w2, w3, w4, w20) * xi;
        o.z = pick6<D + 2>(w0, w1, w2, w3, w4, w20) * xi;
        o.w = pick6<D + 3>(w0, w1, w2, w3, w4, w20) * xi;
        // (base + i0 + D) % 4 == 0 by construction -> aligned STG.128
        __stcs(reinterpret_cast<float4*>(outb + base + i0 + D) + t, o);
    }
}

// 5 clamped LDG.128 + 1 clamped scalar load for one 16-row tile window.
__device__ __forceinline__ void load_window(const float4* __restrict__ xr4,
                                            const float* __restrict__ xrow,
                                            int i0, int t,
                                            float4& w0, float4& w1, float4& w2,
                                            float4& w3, float4& w4, float& w20) {
    // Clamp t (inactive lanes) and overfetch words; clamped slots are only
    // consumed by lanes/rows whose predicate is false (if t < n_r, every
    // needed x index i0+4t+k <= N-1, so its containing word <= M4LAST and
    // the scalar index <= N-1: clamps never feed active data).
    const int tc = t > M4LAST ? M4LAST : t;
    const int m  = (i0 >> 2) + tc;
    const int mc = m > M4LAST ? M4LAST : m;
    w0 = __ldg(xr4 + mc);
    w1 = __ldg(xr4 + (mc + 1 > M4LAST ? M4LAST : mc + 1));
    w2 = __ldg(xr4 + (mc + 2 > M4LAST ? M4LAST : mc + 2));
    w3 = __ldg(xr4 + (mc + 3 > M4LAST ? M4LAST : mc + 3));
    w4 = __ldg(xr4 + (mc + 4 > M4LAST ? M4LAST : mc + 4));
    const int s = 4 * mc + 20;
    w20 = __ldg(xrow + (s > N - 1 ? N - 1 : s));
}

__device__ __forceinline__ void store_tile16(bool ok,
                                             const float4& w0, const float4& w1,
                                             const float4& w2, const float4& w3,
                                             const float4& w4, float w20,
                                             const float4* __restrict__ xr4,
                                             float* __restrict__ outb,
                                             int i0, int t) {
    const float4 xq0 = __ldg(xr4 + (i0 >> 2));        // x[i0   .. i0+3 ]
    const float4 xq1 = __ldg(xr4 + (i0 >> 2) + 1);    // x[i0+4 .. i0+7 ]
    const float4 xq2 = __ldg(xr4 + (i0 >> 2) + 2);    // x[i0+8 .. i0+11]
    const float4 xq3 = __ldg(xr4 + (i0 >> 2) + 3);    // x[i0+12.. i0+15]
    tile_row<0 >(ok, w0, w1, w2, w3, w4, w20, xq0, xq1, xq2, xq3, outb, i0, t);
    tile_row<1 >(ok, w0, w1, w2, w3, w4, w20, xq0, xq1, xq2, xq3, outb, i0, t);
    tile_row<2 >(ok, w0, w1, w2, w3, w4, w20, xq0, xq1, xq2, xq3, outb, i0, t);
    tile_row<3 >(ok, w0, w1, w2, w3, w4, w20, xq0, xq1, xq2, xq3, outb, i0, t);
    tile_row<4 >(ok, w0, w1, w2, w3, w4, w20, xq0, xq1, xq2, xq3, outb, i0, t);
    tile_row<5 >(ok, w0, w1, w2, w3, w4, w20, xq0, xq1, xq2, xq3, outb, i0, t);
    tile_row<6 >(ok, w0, w1, w2, w3, w4, w20, xq0, xq1, xq2, xq3, outb, i0, t);
    tile_row<7 >(ok, w0, w1, w2, w3, w4, w20, xq0, xq1, xq2, xq3, outb, i0, t);
    tile_row<8 >(ok, w0, w1, w2, w3, w4, w20, xq0, xq1, xq2, xq3, outb, i0, t);
    tile_row<9 >(ok, w0, w1, w2, w3, w4, w20, xq0, xq1, xq2, xq3, outb, i0, t);
    tile_row<10>(ok, w0, w1, w2, w3, w4, w20, xq0, xq1, xq2, xq3, outb, i0, t);
    tile_row<11>(ok, w0, w1, w2, w3, w4, w20, xq0, xq1, xq2, xq3, outb, i0, t);
    tile_row<12>(ok, w0, w1, w2, w3, w4, w20, xq0, xq1, xq2, xq3, outb, i0, t);
    tile_row<13>(ok, w0, w1, w2, w3, w4, w20, xq0, xq1, xq2, xq3, outb, i0, t);
    tile_row<14>(ok, w0, w1, w2, w3, w4, w20, xq0, xq1, xq2, xq3, outb, i0, t);
    tile_row<15>(ok, w0, w1, w2, w3, w4, w20, xq0, xq1, xq2, xq3, outb, i0, t);
}

__global__ __launch_bounds__(THREADS)
void selmul_kernel(const float* __restrict__ x, float* __restrict__ out) {
    const int q   = blockIdx.x;        // 0..31
    const int i0A = 16 * q;            // 0..496
    const int i0B = 1008 - 16 * q;     // 1008..512  (both % 16 == 0)
    const int t   = threadIdx.x;
    const int tr  = THREADS - 1 - t;   // reversed lanes for mirror tile:
                                       // nmaxA + nmaxB = 260 ~ 256 lanes.

    for (int bb = 0; bb < BB; ++bb) {
        const int b = blockIdx.y * BB + bb;
        const float*  xrow = x + b * N;
        const float4* xr4  = reinterpret_cast<const float4*>(xrow);
        float* outb = out + b * TRI;   // max elem offset < 2^27: int-safe

        // Scalar heads + tails for the 32 rows of both tiles (<= 6 elems each;
        // rows with fj >= N are covered entirely here).
        if (t < 32) {
            const int i0 = (t & 16) ? i0B : i0A;
            const int i  = i0 + (t & 15);
            const int Tn = triang(i + 1);
            const int base = i * N - Tn;
            const int fj = i + ((((Tn & 3) - (i & 3)) + 4) & 3); // first aligned j
            const float xi = __ldg(xrow + i);
            const int he = fj < N ? fj : N;
            for (int j = i; j < he; ++j)
                __stcs(outb + base + j, xi * __ldg(xrow + j));
            const int nv = (N > fj) ? ((N - fj) >> 2) : 0;
            for (int j = fj + 4 * nv; j < N; ++j)
                __stcs(outb + base + j, xi * __ldg(xrow + j));
        }

        // ---- all window loads first (independent LDGs -> MLP) ----
        const bool okA = t  < ((N - i0A) >> 2);
        const bool okB = tr < ((N - i0B) >> 2);

        float4 a0, a1, a2, a3, a4, c0, c1, c2, c3, c4;
        float a20, c20;
        load_window(xr4, xrow, i0A, t,  a0, a1, a2, a3, a4, a20);
        load_window(xr4, xrow, i0B, tr, c0, c1, c2, c3, c4, c20);

        // ---- then the 32 predicated stores (xq loaded lazily, L1-hit) ----
        store_tile16(okA, a0, a1, a2, a3, a4, a20, xr4, outb, i0A, t);
        store_tile16(okB, c0, c1, c2, c3, c4, c20, xr4, outb, i0B, tr);
    }
}

extern "C" void kernel_launch(void* const* d_in, const int* in_sizes, int n_in,
                              void* d_out, int out_size) {
    (void)in_sizes; (void)n_in; (void)out_size;
    const float* x = (const float*)d_in[0];
    float* out = (float*)d_out;

    dim3 grid(N / 32, B / BB);   // 32 tile-pairs x 64 batch groups = 2048 blocks
    dim3 block(THREADS);
    selmul_kernel<<<grid, block>>>(x, out);
}

// round 14
// speedup vs baseline: 1.0576x; 1.0576x over previous
#include <cuda_runtime.h>

// SelMul: pair (i,j), i<=j, row-major triangular:
//   offset(i,j) = i*N - T(i+1) + j,  T(k) = k(k-1)/2,  value x[b,i]*x[b,j].
// x: (256,1024) fp32 -> out: (256,524800) fp32 (~537 MB). Store-bound.
//
// R13 = R10 (best passing: 88.6us; 8-row fused mirror octets, 4096 CTAs)
// with two occupancy-directed changes:
//  - __launch_bounds__(256, 5): cap regs ~52 -> 5 CTAs/SM (62.5% occ vs 40.7%
//    at regs=64/4 CTAs). R10 profile: DRAM 67.8 / L1 67.9 / issue 37 — nothing
//    saturated -> latency exposure; more resident warps is the lever.
//  - xq (xi vector) loads moved INSIDE each store_octet (lazy, L1-hit) so the
//    load->store boundary cross-section is only the 8 window float4s, giving
//    ptxas room to fit the budget without spilling.
// Indexing identical to R8/R10 (proven): octet rows i0..i0+7, i0%8==0;
//   D(r) = r + ((T(r+1)&3 - r) & 3) = {0,1,3,6,6,7,9,8}, max D+3 = 12.
// Window t: w[0..15] = x[i0+4t..i0+4t+15] (4 aligned LDG.128, clamped
// overfetch only feeds predicated-off lanes); row r emits one aligned STG.128.
// Heads/tails (<=3+3 elems) scalar, same congruence -> exact coverage.

static constexpr int N       = 1024;
static constexpr int B       = 256;
static constexpr int TRI     = N * (N + 1) / 2;   // 524800
static constexpr int BB      = 4;                 // batches per block
static constexpr int THREADS = 256;
static constexpr int M4LAST  = N / 4 - 1;         // 255

__host__ __device__ constexpr int triang(int k) { return k * (k - 1) / 2; }
__host__ __device__ constexpr int Dof(int r) {
    return r + ((((triang(r + 1) & 3) - r) + 8) & 3);
}

template <int K>
__device__ __forceinline__ float pick(const float4& a, const float4& b,
                                      const float4& c, const float4& d) {
    static_assert(K >= 0 && K <= 15);
    if constexpr (K == 0)  return a.x;
    else if constexpr (K == 1)  return a.y;
    else if constexpr (K == 2)  return a.z;
    else if constexpr (K == 3)  return a.w;
    else if constexpr (K == 4)  return b.x;
    else if constexpr (K == 5)  return b.y;
    else if constexpr (K == 6)  return b.z;
    else if constexpr (K == 7)  return b.w;
    else if constexpr (K == 8)  return c.x;
    else if constexpr (K == 9)  return c.y;
    else if constexpr (K == 10) return c.z;
    else if constexpr (K == 11) return c.w;
    else if constexpr (K == 12) return d.x;
    else if constexpr (K == 13) return d.y;
    else if constexpr (K == 14) return d.z;
    else return d.w;
}

template <int R>
__device__ __forceinline__ void octet_row(bool lane_ok,
                                          const float4& w0, const float4& w1,
                                          const float4& w2, const float4& w3,
                                          const float4& xq0, const float4& xq1,
                                          float* __restrict__ outb,
                                          int i0, int t) {
    constexpr int D = Dof(R);
    static_assert(D + 3 <= 15);
    const int v = N - i0 - D;            // 4*n_r (may be <= 0 for last octet)
    if (lane_ok && v > 0 && t < (v >> 2)) {
        const int i = i0 + R;
        const float xi = pick<R>(xq0, xq1, xq1, xq1);       // x[i0+R]
        const int base = i * N - triang(i + 1);
        float4 o;
        o.x = pick<D    >(w0, w1, w2, w3) * xi;
        o.y = pick<D + 1>(w0, w1, w2, w3) * xi;
        o.z = pick<D + 2>(w0, w1, w2, w3) * xi;
        o.w = pick<D + 3>(w0, w1, w2, w3) * xi;
        // (base + i0 + D) % 4 == 0 by construction -> aligned STG.128
        __stcs(reinterpret_cast<float4*>(outb + base + i0 + D) + t, o);
    }
}

// 4 clamped window loads for one octet (no stores).
__device__ __forceinline__ void load_window(const float4* __restrict__ xr4,
                                            int i0, int t,
                                            float4& w0, float4& w1,
                                            float4& w2, float4& w3) {
    // Clamp t (inactive lanes) and the overfetch words; a clamped slot is
    // only consumed by a lane/row whose predicate is false.
    const int tc = t > M4LAST ? M4LAST : t;
    const int m  = (i0 >> 2) + tc;
    const int mc = m > M4LAST ? M4LAST : m;
    w0 = __ldg(xr4 + mc);
    w1 = __ldg(xr4 + (mc + 1 > M4LAST ? M4LAST : mc + 1));
    w2 = __ldg(xr4 + (mc + 2 > M4LAST ? M4LAST : mc + 2));
    w3 = __ldg(xr4 + (mc + 3 > M4LAST ? M4LAST : mc + 3));
}

// 8 predicated rows of one octet; xq loaded here (lazy, L1-hit) to keep the
// load->store boundary cross-section small for the register budget.
__device__ __forceinline__ void store_octet(bool ok,
                                            const float4& w0, const float4& w1,
                                            const float4& w2, const float4& w3,
                                            const float4* __restrict__ xr4,
                                            float* __restrict__ outb,
                                            int i0, int t) {
    const float4 xq0 = __ldg(xr4 + (i0 >> 2));       // x[i0..i0+3]
    const float4 xq1 = __ldg(xr4 + (i0 >> 2) + 1);   // x[i0+4..i0+7]
    octet_row<0>(ok, w0, w1, w2, w3, xq0, xq1, outb, i0, t);
    octet_row<1>(ok, w0, w1, w2, w3, xq0, xq1, outb, i0, t);
    octet_row<2>(ok, w0, w1, w2, w3, xq0, xq1, outb, i0, t);
    octet_row<3>(ok, w0, w1, w2, w3, xq0, xq1, outb, i0, t);
    octet_row<4>(ok, w0, w1, w2, w3, xq0, xq1, outb, i0, t);
    octet_row<5>(ok, w0, w1, w2, w3, xq0, xq1, outb, i0, t);
    octet_row<6>(ok, w0, w1, w2, w3, xq0, xq1, outb, i0, t);
    octet_row<7>(ok, w0, w1, w2, w3, xq0, xq1, outb, i0, t);
}

__global__ __launch_bounds__(THREADS, 5)
void selmul_kernel(const float* __restrict__ x, float* __restrict__ out) {
    const int q   = blockIdx.x;        // 0..63
    const int i0A = 8 * q;             // 0..504
    const int i0B = 1016 - 8 * q;      // 1016..512  (both % 8 == 0)
    const int t   = threadIdx.x;
    const int tr  = THREADS - 1 - t;   // reversed lanes for mirror octet

    for (int bb = 0; bb < BB; ++bb) {
        const int b = blockIdx.y * BB + bb;
        const float*  xrow = x + b * N;
        const float4* xr4  = reinterpret_cast<const float4*>(xrow);
        float* outb = out + b * TRI;   // max elem offset < 2^27: int-safe

        // Scalar heads + tails for the 16 rows of both octets (<= 6 elems each).
        if (t < 16) {
            const int i0 = (t & 8) ? i0B : i0A;
            const int i  = i0 + (t & 7);
            const int Tn = triang(i + 1);
            const int base = i * N - Tn;
            const int fj = i + ((((Tn & 3) - (i & 3)) + 4) & 3); // first aligned j
            const float xi = __ldg(xrow + i);
            const int he = fj < N ? fj : N;
            for (int j = i; j < he; ++j)
                __stcs(outb + base + j, xi * __ldg(xrow + j));
            const int nv = (N > fj) ? ((N - fj) >> 2) : 0;
            for (int j = fj + 4 * nv; j < N; ++j)
                __stcs(outb + base + j, xi * __ldg(xrow + j));
        }

        // ---- all 8 window loads first (independent LDG.128 -> MLP) ----
        const bool okA = t  < ((N - i0A) >> 2);
        const bool okB = tr < ((N - i0B) >> 2);

        float4 a0, a1, a2, a3, b0, b1, b2, b3;
        load_window(xr4, i0A, t,  a0, a1, a2, a3);
        load_window(xr4, i0B, tr, b0, b1, b2, b3);

        // ---- then all stores (predicated, no branches) ----
        store_octet(okA, a0, a1, a2, a3, xr4, outb, i0A, t);
        store_octet(okB, b0, b1, b2, b3, xr4, outb, i0B, tr);
    }
}

extern "C" void kernel_launch(void* const* d_in, const int* in_sizes, int n_in,
                              void* d_out, int out_size) {
    (void)in_sizes; (void)n_in; (void)out_size;
    const float* x = (const float*)d_in[0];
    float* out = (float*)d_out;

    dim3 grid(N / 16, B / BB);   // 64 octet-pairs x 64 batch groups = 4096 blocks
    dim3 block(THREADS);
    selmul_kernel<<<grid, block>>>(x, out);
}

// round 15
// speedup vs baseline: 1.1071x; 1.0468x over previous
#include <cuda_runtime.h>

// SelMul: pair (i,j), i<=j, row-major triangular:
//   offset(i,j) = i*N - T(i+1) + j,  T(k) = k(k-1)/2,  value x[b,i]*x[b,j].
// x: (256,1024) fp32 -> out: (256,524800) fp32 (~537 MB). Store-bound.
//
// R14 = R13 (8-row fused mirror octets, launch_bounds(256,5), lazy xq) plus:
//  - warp-uniform early-skip: warps with no active lanes for an octet skip its
//    loads AND stores (mirror lane-reversal makes predicates warp-contiguous:
//    low warps serve octet A, high warps serve octet B). Halves issued
//    store/load instructions (R13: issue 46.9% with ~half predicated off).
//  - BB=2 -> 8192 CTAs -> ~11 waves at 5 CTAs/SM: wave-quantization tail ~1%
//    (R13: 5.5 waves -> ~10% tail, achieved occ 52.6 < 62.5 theoretical).
// Indexing identical to R8/R10/R13 (proven): octet rows i0..i0+7, i0%8==0;
//   D(r) = r + ((T(r+1)&3 - r) & 3) = {0,1,3,6,6,7,9,8}, max D+3 = 12.
// Window t: w[0..15] = x[i0+4t..i0+4t+15] (4 aligned LDG.128, clamped
// overfetch only feeds predicated-off lanes); row r emits one aligned STG.128.
// Heads/tails (<=3+3 elems) scalar, same congruence -> exact coverage.

static constexpr int N       = 1024;
static constexpr int B       = 256;
static constexpr int TRI     = N * (N + 1) / 2;   // 524800
static constexpr int BB      = 2;                 // batches per block
static constexpr int THREADS = 256;
static constexpr int M4LAST  = N / 4 - 1;         // 255

__host__ __device__ constexpr int triang(int k) { return k * (k - 1) / 2; }
__host__ __device__ constexpr int Dof(int r) {
    return r + ((((triang(r + 1) & 3) - r) + 8) & 3);
}

template <int K>
__device__ __forceinline__ float pick(const float4& a, const float4& b,
                                      const float4& c, const float4& d) {
    static_assert(K >= 0 && K <= 15);
    if constexpr (K == 0)  return a.x;
    else if constexpr (K == 1)  return a.y;
    else if constexpr (K == 2)  return a.z;
    else if constexpr (K == 3)  return a.w;
    else if constexpr (K == 4)  return b.x;
    else if constexpr (K == 5)  return b.y;
    else if constexpr (K == 6)  return b.z;
    else if constexpr (K == 7)  return b.w;
    else if constexpr (K == 8)  return c.x;
    else if constexpr (K == 9)  return c.y;
    else if constexpr (K == 10) return c.z;
    else if constexpr (K == 11) return c.w;
    else if constexpr (K == 12) return d.x;
    else if constexpr (K == 13) return d.y;
    else if constexpr (K == 14) return d.z;
    else return d.w;
}

template <int R>
__device__ __forceinline__ void octet_row(bool lane_ok,
                                          const float4& w0, const float4& w1,
                                          const float4& w2, const float4& w3,
                                          const float4& xq0, const float4& xq1,
                                          float* __restrict__ outb,
                                          int i0, int t) {
    constexpr int D = Dof(R);
    static_assert(D + 3 <= 15);
    const int v = N - i0 - D;            // 4*n_r (may be <= 0 for last octet)
    if (lane_ok && v > 0 && t < (v >> 2)) {
        const int i = i0 + R;
        const float xi = pick<R>(xq0, xq1, xq1, xq1);       // x[i0+R]
        const int base = i * N - triang(i + 1);
        float4 o;
        o.x = pick<D    >(w0, w1, w2, w3) * xi;
        o.y = pick<D + 1>(w0, w1, w2, w3) * xi;
        o.z = pick<D + 2>(w0, w1, w2, w3) * xi;
        o.w = pick<D + 3>(w0, w1, w2, w3) * xi;
        // (base + i0 + D) % 4 == 0 by construction -> aligned STG.128
        __stcs(reinterpret_cast<float4*>(outb + base + i0 + D) + t, o);
    }
}

// One octet: 4 clamped window loads + 8 predicated row stores.
// Caller guarantees at least one lane in the warp is active.
__device__ __forceinline__ void do_octet(const float4* __restrict__ xr4,
                                         float* __restrict__ outb,
                                         int i0, int t, bool ok) {
    const int tc = t > M4LAST ? M4LAST : t;
    const int m  = (i0 >> 2) + tc;
    const int mc = m > M4LAST ? M4LAST : m;
    // Clamped overfetch: a clamped slot is only consumed by a lane/row whose
    // predicate is false.
    const float4 w0 = __ldg(xr4 + mc);
    const float4 w1 = __ldg(xr4 + (mc + 1 > M4LAST ? M4LAST : mc + 1));
    const float4 w2 = __ldg(xr4 + (mc + 2 > M4LAST ? M4LAST : mc + 2));
    const float4 w3 = __ldg(xr4 + (mc + 3 > M4LAST ? M4LAST : mc + 3));
    const float4 xq0 = __ldg(xr4 + (i0 >> 2));       // x[i0..i0+3]
    const float4 xq1 = __ldg(xr4 + (i0 >> 2) + 1);   // x[i0+4..i0+7]
    octet_row<0>(ok, w0, w1, w2, w3, xq0, xq1, outb, i0, t);
    octet_row<1>(ok, w0, w1, w2, w3, xq0, xq1, outb, i0, t);
    octet_row<2>(ok, w0, w1, w2, w3, xq0, xq1, outb, i0, t);
    octet_row<3>(ok, w0, w1, w2, w3, xq0, xq1, outb, i0, t);
    octet_row<4>(ok, w0, w1, w2, w3, xq0, xq1, outb, i0, t);
    octet_row<5>(ok, w0, w1, w2, w3, xq0, xq1, outb, i0, t);
    octet_row<6>(ok, w0, w1, w2, w3, xq0, xq1, outb, i0, t);
    octet_row<7>(ok, w0, w1, w2, w3, xq0, xq1, outb, i0, t);
}

__global__ __launch_bounds__(THREADS, 5)
void selmul_kernel(const float* __restrict__ x, float* __restrict__ out) {
    const int q   = blockIdx.x;        // 0..63
    const int i0A = 8 * q;             // 0..504
    const int i0B = 1016 - 8 * q;      // 1016..512  (both % 8 == 0)
    const int t   = threadIdx.x;
    const int tr  = THREADS - 1 - t;   // reversed lanes for mirror octet:
                                       // low warps serve A, high warps serve B.

    for (int bb = 0; bb < BB; ++bb) {
        const int b = blockIdx.y * BB + bb;
        const float*  xrow = x + b * N;
        const float4* xr4  = reinterpret_cast<const float4*>(xrow);
        float* outb = out + b * TRI;   // max elem offset < 2^27: int-safe

        // Scalar heads + tails for the 16 rows of both octets (<= 6 elems each).
        if (t < 16) {
            const int i0 = (t & 8) ? i0B : i0A;
            const int i  = i0 + (t & 7);
            const int Tn = triang(i + 1);
            const int base = i * N - Tn;
            const int fj = i + ((((Tn & 3) - (i & 3)) + 4) & 3); // first aligned j
            const float xi = __ldg(xrow + i);
            const int he = fj < N ? fj : N;
            for (int j = i; j < he; ++j)
                __stcs(outb + base + j, xi * __ldg(xrow + j));
            const int nv = (N > fj) ? ((N - fj) >> 2) : 0;
            for (int j = fj + 4 * nv; j < N; ++j)
                __stcs(outb + base + j, xi * __ldg(xrow + j));
        }

        const bool okA = t  < ((N - i0A) >> 2);
        const bool okB = tr < ((N - i0B) >> 2);

        // Warp-uniform skip: predicates are warp-contiguous (lane reversal),
        // so most warps execute exactly one of the two octets.
        const bool anyA = __any_sync(0xffffffffu, okA);
        const bool anyB = __any_sync(0xffffffffu, okB);
        if (anyA) do_octet(xr4, outb, i0A, t,  okA);
        if (anyB) do_octet(xr4, outb, i0B, tr, okB);
    }
}

extern "C" void kernel_launch(void* const* d_in, const int* in_sizes, int n_in,
                              void* d_out, int out_size) {
    (void)in_sizes; (void)n_in; (void)out_size;
    const float* x = (const float*)d_in[0];
    float* out = (float*)d_out;

    dim3 grid(N / 16, B / BB);   // 64 octet-pairs x 128 batch groups = 8192 blocks
    dim3 block(THREADS);
    selmul_kernel<<<grid, block>>>(x, out);
}